// round 17
// baseline (speedup 1.0000x reference)
#include <cuda_runtime.h>

// Nosé–Hoover chain (N_CHAIN=2) velocity-Verlet, B=1024, NDOF=64, 200 steps.
// Out: [traj_x (201,1024,64) | traj_v (201,1024,64)] fp32.
//
// R17: free-running producer + polling consumers (fixes R15's lock-step).
// The ~18us invariant across R5/R15/R16 is the thermostat chain's serial
// latency re-exposed per step/batch. Here the producer warp streams ALL 200
// sv values into a full-size smem buffer (6.4KB), bumping an acquire/release
// progress counter every 8 steps; consumer warps poll and consume 8-step
// chunks, running a constant ~8 steps behind. No steady-state barriers.
//  Block = 160 thr: warps 0-3 consume (2 systems each, 16 lanes/sys, float4/
//  lane packed f32x2); warp 4 produces (lanes 0-7 = 8 systems' chains SIMT).
//  Stores stay st.global.cs (R16). Const-specialized kT=mass=Q=1 fast path.

namespace {
constexpr int NSYS   = 1024;
constexpr int NSTEP  = 200;
constexpr int CHUNK  = 8;
constexpr int NCHUNK = NSTEP / CHUNK;       // 25
constexpr int SPB    = 8;                   // systems per block
constexpr int F4SYS  = 16;                  // float4 per system
constexpr int F4SNAP = NSYS * F4SYS;        // 16384 float4 per snapshot
}

#define FMA2(d,a,b,c) asm("fma.rn.f32x2 %0,%1,%2,%3;" : "=l"(d) : "l"(a), "l"(b), "l"(c))
#define MUL2(d,a,b)   asm("mul.rn.f32x2 %0,%1,%2;"    : "=l"(d) : "l"(a), "l"(b))
#define PACK2(d,f)    asm("mov.b64 %0,{%1,%1};"       : "=l"(d) : "f"(f))
#define PACKAB(d,a,b) asm("mov.b64 %0,{%1,%2};"       : "=l"(d) : "f"(a), "f"(b))
#define STG128CS(p,a,b) \
    asm volatile("st.global.cs.v2.b64 [%0],{%1,%2};" :: "l"(p), "l"(a), "l"(b) : "memory")

// exp(-z) for |z| <= ~3e-4: 1 - z + z^2/2  (rel err ~ z^3/6 <= 5e-12)
__device__ __forceinline__ float expm(float z) {
    return fmaf(fmaf(0.5f, z, -1.0f), z, 1.0f);
}

__device__ __forceinline__ unsigned ld_acq(const unsigned* p) {
    unsigned v;
    unsigned long long a = __cvta_generic_to_shared(p);
    asm volatile("ld.acquire.cta.shared.u32 %0,[%1];" : "=r"(v) : "l"(a) : "memory");
    return v;
}
__device__ __forceinline__ void st_rel(unsigned* p, unsigned v) {
    unsigned long long a = __cvta_generic_to_shared(p);
    asm volatile("st.release.cta.shared.u32 [%0],%1;" :: "l"(a), "r"(v) : "memory");
}

__device__ __forceinline__ void run_block(
    float kT, float mass, float Q,
    int wid, int lane, int base,
    const float4* __restrict__ gx0,
    const float4* __restrict__ gv0,
    float4* __restrict__ out,
    float (*s_mom)[4],
    float (*s_sv)[SPB],
    unsigned* s_prog)
{
    const float dt   = 0.002f;
    const float dt4  = 0.25f  * dt;
    const float dt8  = 0.125f * dt;
    const float dth  = 0.5f   * dt;
    const float invQ = 1.0f / Q;
    const float c1   = dth / mass;
    const float A    = 1.0f - dt * c1;
    const float A2   = A * A;
    const float cx0  = -c1 * (1.0f + A);
    const float mIQ  = mass * invQ;
    const float nkIQ = -64.0f * kT * invQ;
    const float kTiQ = kT * invQ;
    const float m0c  = cx0 * cx0;
    const float m1c  = 2.0f * cx0 * A;
    const float p1c  = 2.0f * A * dt;
    const float p2c  = dt * dt;
    const float acx  = A * cx0;
    const float mc   = A2 + dt * cx0;
    const float dA   = dt * A;

    // ---- consumer state ----
    unsigned long long Xp0 = 0, Xp1 = 0, Vp0 = 0, Vp1 = 0, Ap = 0;
    const float4* px = nullptr;
    const float4* pv = nullptr;
    int sysloc = 0;

    if (wid < 4) {
        // ===== consumer setup: load, moments, snapshot 0 =====
        sysloc = 2 * wid + (lane >> 4);               // 0..7
        const int sys = base + sysloc;
        const int idx = sys * F4SYS + (lane & 15);
        const float4 x0 = gx0[idx];
        const float4 v0 = gv0[idx];

        float a = x0.x * x0.x; a = fmaf(x0.y, x0.y, a); a = fmaf(x0.z, x0.z, a); a = fmaf(x0.w, x0.w, a);
        float c = x0.x * v0.x; c = fmaf(x0.y, v0.y, c); c = fmaf(x0.z, v0.z, c); c = fmaf(x0.w, v0.w, c);
        float e = v0.x * v0.x; e = fmaf(v0.y, v0.y, e); e = fmaf(v0.z, v0.z, e); e = fmaf(v0.w, v0.w, e);
        #pragma unroll
        for (int m = 1; m <= 8; m <<= 1) {
            a += __shfl_xor_sync(0xffffffffu, a, m);
            c += __shfl_xor_sync(0xffffffffu, c, m);
            e += __shfl_xor_sync(0xffffffffu, e, m);
        }
        if ((lane & 15) == 0) {
            s_mom[sysloc][0] = a;
            s_mom[sysloc][1] = c;
            s_mom[sysloc][2] = e;
        }

        PACKAB(Xp0, x0.x, x0.y); PACKAB(Xp1, x0.z, x0.w);
        PACKAB(Vp0, v0.x, v0.y); PACKAB(Vp1, v0.z, v0.w);
        PACK2(Ap, A);

        px = out + idx;
        pv = out + (size_t)(NSTEP + 1) * F4SNAP + idx;
        STG128CS(px, Xp0, Xp1);
        STG128CS(pv, Vp0, Vp1);
        px += F4SNAP; pv += F4SNAP;
    }
    __syncthreads();                                   // moments + s_prog=0 visible

    if (wid == 4) {
        // ===== producer: 8 systems' chains SIMT, free-running =====
        const int sl = lane & 7;                       // lanes 8-31 shadow lane&7
        float sxx = s_mom[sl][0];
        float sxv = s_mom[sl][1];
        float svv = s_mom[sl][2];
        float xi0 = 0.0f, xi1 = 0.0f;

        auto chain_step = [&]() -> float {
            float G  = fmaf(mIQ, svv, nkIQ);
            xi1 = fmaf(dt4, G, xi1);
            float G0 = fmaf(xi0, xi0, -kTiQ);
            float z1 = xi1 * dt8;
            float se = expm(z1);
            float s2 = se * se;
            float dt4s = dt4 * se;
            float xi0a = fmaf(xi0, s2, G0 * dt4s);
            float z0 = xi0a * dth;
            float sv  = expm(z0);
            float sv2 = sv * sv;
            float svv_n = sv2 * fmaf(sv2, A2 * svv, fmaf(sv, m1c * sxv, m0c * sxx));
            float G2 = fmaf(mIQ, svv_n, nkIQ);
            xi0 = fmaf(dt4s, G2, xi0a * s2);
            float G3 = fmaf(xi0, xi0, -kTiQ);
            xi1 = fmaf(dt4, G3, xi1);
            float sxx_n = fmaf(p2c * sv2, svv, fmaf(p1c * sv, sxv, A2 * sxx));
            float sxv_n = fmaf((dA * sv) * sv2, svv,
                               fmaf(mc * sv2, sxv, (acx * sv) * sxx));
            sxx = sxx_n; sxv = sxv_n; svv = svv_n;
            return sv;
        };

        for (int c = 0; c < NCHUNK; ++c) {
            #pragma unroll
            for (int k = 0; k < CHUNK; ++k) {
                float sv = chain_step();
                if (lane < SPB) s_sv[c * CHUNK + k][sl] = sv;
            }
            __syncwarp();
            if (lane == 0) st_rel(s_prog, (unsigned)((c + 1) * CHUNK));
        }
        return;
    }

    // ===== consumers: poll progress, consume 8-step chunks =====
    for (int c = 0; c < NCHUNK; ++c) {
        const unsigned need = (unsigned)((c + 1) * CHUNK);
        while (ld_acq(s_prog) < need) { /* spin: cheap LDS */ }

        float svs[CHUNK];
        #pragma unroll
        for (int k = 0; k < CHUNK; ++k)
            svs[k] = s_sv[c * CHUNK + k][sysloc];

        #pragma unroll
        for (int k = 0; k < CHUNK; ++k) {
            float sv  = svs[k];
            float sv2 = sv * sv;
            float B   = dt  * sv;
            float Cx  = cx0 * sv;
            float Cv  = A   * sv2;
            unsigned long long Bp, Cxp, Cvp, t0, t1, u0, u1, xn0, xn1, vn0, vn1;
            PACK2(Bp, B); PACK2(Cxp, Cx); PACK2(Cvp, Cv);
            MUL2(t0, Bp,  Vp0);  MUL2(t1, Bp,  Vp1);
            MUL2(u0, Cvp, Vp0);  MUL2(u1, Cvp, Vp1);
            FMA2(xn0, Ap,  Xp0, t0);  FMA2(xn1, Ap,  Xp1, t1);
            FMA2(vn0, Cxp, Xp0, u0);  FMA2(vn1, Cxp, Xp1, u1);
            Xp0 = xn0; Xp1 = xn1; Vp0 = vn0; Vp1 = vn1;
            STG128CS(px, Xp0, Xp1);
            STG128CS(pv, Vp0, Vp1);
            px += F4SNAP; pv += F4SNAP;
        }
    }
}

__global__ __launch_bounds__(160, 1)
void nhc_kernel(const float4* __restrict__ gx0,
                const float4* __restrict__ gv0,
                const float*  __restrict__ pkT,
                const float*  __restrict__ pmass,
                const float*  __restrict__ pQ,
                float4*       __restrict__ out)
{
    __shared__ float    s_mom[SPB][4];
    __shared__ float    s_sv[NSTEP][SPB];             // 6.4KB, full trajectory
    __shared__ unsigned s_prog;

    const int tid  = threadIdx.x;
    const int lane = tid & 31;
    const int wid  = tid >> 5;                        // 0-3 consumers, 4 producer
    const int base = blockIdx.x * SPB;

    if (tid == 0) s_prog = 0;

    const float kT   = *pkT;
    const float mass = *pmass;
    const float Q    = *pQ;

    if (kT == 1.0f && mass == 1.0f && Q == 1.0f)
        run_block(1.0f, 1.0f, 1.0f, wid, lane, base, gx0, gv0, out,
                  s_mom, s_sv, &s_prog);
    else
        run_block(kT, mass, Q, wid, lane, base, gx0, gv0, out,
                  s_mom, s_sv, &s_prog);
}

extern "C" void kernel_launch(void* const* d_in, const int* in_sizes, int n_in,
                              void* d_out, int out_size)
{
    const float4* x0   = (const float4*)d_in[0];
    const float4* v0   = (const float4*)d_in[1];
    const float*  kT   = (const float*)d_in[2];
    const float*  mass = (const float*)d_in[3];
    const float*  Q    = (const float*)d_in[4];
    float4* out = (float4*)d_out;

    // 1024 systems / 8 per block = 128 blocks x 160 threads (5 warps):
    // 4 consumer warps + 1 free-running producer warp per block
    nhc_kernel<<<NSYS / SPB, 160>>>(x0, v0, kT, mass, Q, out);
}